// round 14
// baseline (speedup 1.0000x reference)
#include <cuda_runtime.h>
#include <cuda_bf16.h>
#include <cstdint>
#include <math.h>

#define T_STEPS 2048
#define B_ROWS  64
#define TNO     501
#define NBASIS  30
#define ACC_N   512     // far-delay accumulator ring (power of 2 > TNO)
#define ACC_M   511
#define NTH     128     // 4 warps: chain / uniform / decision+scatter / init-help

// ---------------------------------------------------------------------------
// Threefry-2x32, 20 rounds — bit-exact port of jax/_src/prng.py threefry2x32
// ---------------------------------------------------------------------------
__device__ __forceinline__ void tf2x32(uint32_t k0, uint32_t k1,
                                       uint32_t x0, uint32_t x1,
                                       uint32_t &o0, uint32_t &o1) {
    uint32_t k2 = k0 ^ k1 ^ 0x1BD11BDAu;
#define TFR(r) { x0 += x1; x1 = __funnelshift_l(x1, x1, (r)); x1 ^= x0; }
    x0 += k0; x1 += k1;
    TFR(13) TFR(15) TFR(26) TFR(6)
    x0 += k1; x1 += k2 + 1u;
    TFR(17) TFR(29) TFR(16) TFR(24)
    x0 += k2; x1 += k0 + 2u;
    TFR(13) TFR(15) TFR(26) TFR(6)
    x0 += k0; x1 += k1 + 3u;
    TFR(17) TFR(29) TFR(16) TFR(24)
    x0 += k1; x1 += k2 + 4u;
    TFR(13) TFR(15) TFR(26) TFR(6)
    x0 += k2; x1 += k0 + 5u;
#undef TFR
    o0 = x0; o1 = x1;
}

// XLA EmitTanh (Eigen rational, clamp [-9,9], |x|<4e-4 -> x), UNcontracted.
// This exact form gave rel_err 8e-8 (zero Bernoulli flips). DO NOT TOUCH.
__device__ __forceinline__ float tanh_xla(float x) {
    float ax = fabsf(x);
    float xc = fminf(fmaxf(x, -9.0f), 9.0f);
    float x2 = __fmul_rn(xc, xc);
    float num = -2.76076847742355e-16f;
    num = __fadd_rn(__fmul_rn(x2, num),  2.00018790482477e-13f);
    num = __fadd_rn(__fmul_rn(x2, num), -8.60467152213735e-11f);
    num = __fadd_rn(__fmul_rn(x2, num),  5.12229709037114e-08f);
    num = __fadd_rn(__fmul_rn(x2, num),  1.48572235717979e-05f);
    num = __fadd_rn(__fmul_rn(x2, num),  6.37261928875436e-04f);
    num = __fadd_rn(__fmul_rn(x2, num),  4.89352455891786e-03f);
    num = __fmul_rn(xc, num);
    float den = 1.19825839466702e-06f;
    den = __fadd_rn(__fmul_rn(x2, den),  1.18534705686654e-04f);
    den = __fadd_rn(__fmul_rn(x2, den),  2.26843463243900e-03f);
    den = __fadd_rn(__fmul_rn(x2, den),  4.89352518554385e-03f);
    float r = __fdiv_rn(num, den);
    return (ax < 0.0004f) ? x : r;
}
// P = 0.5*tanh(0.5*x)+0.5  (bit-identical to the passing kernel's sequence)
__device__ __forceinline__ float sigP(float x) {
    return __fadd_rn(__fmul_rn(0.5f, tanh_xla(__fmul_rn(0.5f, x))), 0.5f);
}

__device__ __forceinline__ void st_rel(int *p, int v) {
    uint32_t a = (uint32_t)__cvta_generic_to_shared(p);
    asm volatile("st.release.cta.shared.b32 [%0], %1;" :: "r"(a), "r"(v) : "memory");
}
__device__ __forceinline__ int ldv(volatile int *p) { return *p; }

// ---------------------------------------------------------------------------
// One block per row b.  4 warps:
//   warp0 lane0   : key-split chain (serial threefry — ~260 cy/step floor)
//   warp1 lanes0-3: uniform producers (4 steps per poll)
//   warp2 (all 32): decision+scatter — lane L computes candidate P(t|mask=L)
//                   (validated R12 sequence); same warp resolves step t-5 via
//                   shfl AND immediately scatters far delays 13..501 of the
//                   resolved spike.  ZERO cross-warp traffic on the recurrence.
//   warp3         : init help only
// Warps 2+3 do init (f64 basis, MLP) then bar.sync 1,64; warps 0,1 free-run.
// ---------------------------------------------------------------------------
__global__ __launch_bounds__(NTH)
void apnn_kernel(const float *__restrict__ V,  const float *__restrict__ D,
                 const float *__restrict__ w1, const float *__restrict__ b1,
                 const float *__restrict__ w2, const float *__restrict__ b2,
                 const float *__restrict__ Wref, float *__restrict__ out) {
    __shared__ float    nnrow[T_STEPS];          // MLP output, this row
    __shared__ uint32_t subring[T_STEPS][2];     // per-step subkeys
    __shared__ float    uring[T_STEPS];          // per-step uniforms
    __shared__ float    acc[ACC_N];              // pending far refract
    __shared__ float    wdel[TNO];               // weight for delay j+1
    __shared__ int      chain_seq, u_seq;

    const int tid = threadIdx.x;
    const int wid = tid >> 5;
    const int b   = blockIdx.x;

    if (tid == 0) { chain_seq = 0; u_seq = 0; }
    __syncthreads();

    if (tid == 0) {
        // ---- chain: free-running serial split chain (R7 verbatim)
        uint32_t k0 = 0u, k1 = 42u;              // jax.random.key(42) -> (0,42)
        for (int base = 0; base < T_STEPS; base += 2) {
            uint32_t nk0, nk1, s0, s1;
            tf2x32(k0, k1, 0u, 0u, nk0, nk1);
            tf2x32(k0, k1, 0u, 1u, s0, s1);
            subring[base][0] = s0;  subring[base][1] = s1;
            k0 = nk0; k1 = nk1;
            tf2x32(k0, k1, 0u, 0u, nk0, nk1);
            tf2x32(k0, k1, 0u, 1u, s0, s1);
            subring[base + 1][0] = s0;  subring[base + 1][1] = s1;
            k0 = nk0; k1 = nk1;
            st_rel(&chain_seq, base + 2);
        }
    } else if (tid >= 32 && tid < 36) {
        // ---- uniform: 4 lanes, 4 steps per poll (R7 verbatim)
        const int lane = tid - 32;
        int cs = 0;
        for (int base = 0; base < T_STEPS; base += 4) {
            if (cs < base + 4) { do { cs = ldv(&chain_seq); } while (cs < base + 4); }
            int t = base + lane;
            uint32_t s0 = subring[t][0];
            uint32_t s1 = subring[t][1];
            uint32_t y0, y1;
            tf2x32(s0, s1, 0u, (uint32_t)b, y0, y1);
            uint32_t bits = y0 ^ y1;
            uring[t] = __uint_as_float((bits >> 9) | 0x3F800000u) - 1.0f;
            __syncwarp(0xFu);
            if (lane == 0) st_rel(&u_seq, base + 4);
        }
    } else if (tid >= 64) {
        // ---- init on warps 2+3 (64 threads), overlapped with chain/uniform
        const int itid = tid - 64;
        for (int i = itid; i < ACC_N; i += 64) acc[i] = 0.0f;
        // refractory delay weights: wdel[j] = sum_i f32(basis_f64[i,j])*Wref[i]
        for (int j = itid; j < TNO; j += 64) {
            double raw = 7.5 * log(((double)j + 1.0) + 1e-7);
            double cr = cos(raw), sr = sin(raw);
            float s = 0.0f;
            #pragma unroll 1
            for (int i = 0; i < NBASIS; i++) {
                double phi = 1.5707963267948966 * (double)i;
                float bas = 0.0f;
                if (!(raw < phi - 3.141592653589793 || raw > phi + 3.141592653589793)) {
                    double cv;
                    switch (i & 3) {
                        case 0:  cv =  cr; break;
                        case 1:  cv =  sr; break;
                        case 2:  cv = -cr; break;
                        default: cv = -sr; break;
                    }
                    bas = (float)(0.5 * cv + 0.5);
                }
                s = __fmaf_rn(bas, Wref[i], s);
            }
            wdel[j] = s;
        }
        // pointwise MLP (R7 verbatim math)
        {
            float a0 = w1[0], a1 = w1[1], a2 = w1[2], a3 = w1[3], a4 = w1[4];
            float a5 = w1[5], a6 = w1[6], a7 = w1[7], a8 = w1[8], a9 = w1[9];
            float c0 = b1[0], c1 = b1[1], c2 = b1[2], c3 = b1[3], c4 = b1[4];
            float v0 = w2[0], v1 = w2[1], v2 = w2[2], v3 = w2[3], v4 = w2[4];
            float bb = b2[0];
            const float *Vr = V + (size_t)b * T_STEPS;
            const float *Dr = D + (size_t)b * T_STEPS;
            for (int t = itid; t < T_STEPS; t += 64) {
                float vv = Vr[t], dd = Dr[t];
                float h0 = tanh_xla(__fadd_rn(__fadd_rn(__fmul_rn(a0, vv), __fmul_rn(a1, dd)), c0));
                float h1 = tanh_xla(__fadd_rn(__fadd_rn(__fmul_rn(a2, vv), __fmul_rn(a3, dd)), c1));
                float h2 = tanh_xla(__fadd_rn(__fadd_rn(__fmul_rn(a4, vv), __fmul_rn(a5, dd)), c2));
                float h3 = tanh_xla(__fadd_rn(__fadd_rn(__fmul_rn(a6, vv), __fmul_rn(a7, dd)), c3));
                float h4 = tanh_xla(__fadd_rn(__fadd_rn(__fmul_rn(a8, vv), __fmul_rn(a9, dd)), c4));
                float s = __fmul_rn(v0, h0);
                s = __fadd_rn(s, __fmul_rn(v1, h1));
                s = __fadd_rn(s, __fmul_rn(v2, h2));
                s = __fadd_rn(s, __fmul_rn(v3, h3));
                s = __fadd_rn(s, __fmul_rn(v4, h4));
                nnrow[t] = __fadd_rn(s, bb);
            }
        }
        asm volatile("bar.sync 1, 64;" ::: "memory");   // warps 2+3

        if (wid == 2) {
            // ---- decision+scatter warp (single warp owns the full recurrence)
            const int lane = tid & 31;
            const bool c0 = lane & 1, c1 = lane & 2, c2 = lane & 4,
                       c3 = lane & 8, c4 = lane & 16;
            const float wd0 = wdel[0],  wd1 = wdel[1],  wd2 = wdel[2];
            const float wd3 = wdel[3],  wd4 = wdel[4],  wd5 = wdel[5];
            const float wd6 = wdel[6],  wd7 = wdel[7],  wd8 = wdel[8];
            const float wd9 = wdel[9],  wd10 = wdel[10], wd11 = wdel[11];
            // far-scatter weights: delay d = 13 + lane + 32*j
            float wreg[16];
            #pragma unroll
            for (int j = 0; j < 16; j++) {
                int d = 13 + lane + 32 * j;
                wreg[j] = (d <= TNO) ? wdel[d - 1] : 0.0f;
            }
            float g6 = 0.f, g7 = 0.f, g8 = 0.f, g9 = 0.f,
                  g10 = 0.f, g11 = 0.f, g12 = 0.f;
            float Pc[8];                       // candidate regs (static idx only)
            #pragma unroll
            for (int i = 0; i < 8; i++) Pc[i] = 0.f;
            float sp_prev = 0.f;               // s(t-6) for next slot's g-update
            unsigned m = 0;                    // realized mask bits s(t5-1..t5-5)
            float *Sout = out + (size_t)b * T_STEPS;
            float *Pout = out + (size_t)B_ROWS * T_STEPS + (size_t)b * T_STEPS;
            int us = 0;
            for (int B = 0; B < T_STEPS; B += 8) {
                if (us < B + 3) { do { us = ldv(&u_seq); } while (us < B + 3); }
                // preload u(t5) for t5 = B-5..B+2 and nn for t = B..B+7
                float uu[8], nnv[8];
                #pragma unroll
                for (int q = 0; q < 8; q++) {
                    int i5 = B + q - 5;
                    uu[q] = uring[i5 < 0 ? 0 : i5];
                }
                #pragma unroll
                for (int q = 0; q < 8; q++) nnv[q] = nnrow[B + q];
                #pragma unroll
                for (int p = 0; p < 8; p++) {
                    const int t = B + p;
                    // tail update with s(t-6) (resolved at previous slot)
                    g6  = __fmaf_rn(wd5,  sp_prev, g7);
                    g7  = __fmaf_rn(wd6,  sp_prev, g8);
                    g8  = __fmaf_rn(wd7,  sp_prev, g9);
                    g9  = __fmaf_rn(wd8,  sp_prev, g10);
                    g10 = __fmaf_rn(wd9,  sp_prev, g11);
                    g11 = __fmaf_rn(wd10, sp_prev, g12);
                    g12 = __fmul_rn(wd11, sp_prev);
                    // far accumulator for step t: scatters from resolves <= t-13
                    // happened >= 8 slots earlier in THIS warp (program order).
                    int sl = t & ACC_M;
                    float far = acc[sl];
                    if (lane == 0) acc[sl] = 0.0f;   // recycle for t+512
                    // candidate (validated rounding sequence)
                    float v = g6;
                    if (c4) v = __fadd_rn(wd4, v);
                    if (c3) v = __fadd_rn(wd3, v);
                    if (c2) v = __fadd_rn(wd2, v);
                    if (c1) v = __fadd_rn(wd1, v);
                    if (c0) v = __fadd_rn(wd0, v);
                    float x = __fadd_rn(nnv[p], __fadd_rn(far, v));
                    float newP = sigP(x);
                    // resolve step t-5 (candidate from 5 slots ago)
                    float P = __shfl_sync(0xFFFFFFFFu, Pc[(p + 3) & 7], (int)m);
                    int t5 = t - 5;
                    if (t5 >= 0) {                    // uniform; false only B=0,p<5
                        bool  sp  = (uu[p] < P);
                        float spf = sp ? 1.0f : 0.0f;
                        if (lane == 0) {
                            Sout[t5] = spf;
                            Pout[t5] = P;
                        }
                        m = ((m << 1) | (sp ? 1u : 0u)) & 31u;
                        sp_prev = spf;
                        // in-warp far scatter of resolved spike (uniform branch)
                        if (sp) {
                            #pragma unroll
                            for (int j = 0; j < 16; j++) {
                                int d = 13 + lane + 32 * j;
                                if (d <= TNO) {
                                    int s2 = (t5 + d) & ACC_M;   // conflict-free
                                    acc[s2] = __fmaf_rn(wreg[j], spf, acc[s2]);
                                }
                            }
                        }
                    } else {
                        sp_prev = 0.f;
                    }
                    Pc[p] = newP;
                }
            }
            // epilogue: resolve last 5 steps (t5 = T-5..T-1), cands in Pc[3..7]
            if (us < T_STEPS) { do { us = ldv(&u_seq); } while (us < T_STEPS); }
            #pragma unroll
            for (int p2 = 0; p2 < 5; p2++) {
                int t5 = T_STEPS - 5 + p2;
                float P = __shfl_sync(0xFFFFFFFFu, Pc[3 + p2], (int)m);
                bool  sp  = (uring[t5] < P);
                float spf = sp ? 1.0f : 0.0f;
                if (lane == 0) {
                    Sout[t5] = spf;
                    Pout[t5] = P;
                }
                m = ((m << 1) | (sp ? 1u : 0u)) & 31u;
                // no scatter needed: no future steps consume it
            }
        }
        // warp3: done after init/bar
    }
}

extern "C" void kernel_launch(void* const* d_in, const int* in_sizes, int n_in,
                              void* d_out, int out_size) {
    const float *V    = (const float*)d_in[0];
    const float *D    = (const float*)d_in[1];
    const float *w1   = (const float*)d_in[2];
    const float *b1   = (const float*)d_in[3];
    const float *w2   = (const float*)d_in[4];
    const float *b2   = (const float*)d_in[5];
    const float *Wref = (const float*)d_in[6];
    float *out = (float*)d_out;
    apnn_kernel<<<B_ROWS, NTH>>>(V, D, w1, b1, w2, b2, Wref, out);
}

// round 16
// speedup vs baseline: 1.0526x; 1.0526x over previous
#include <cuda_runtime.h>
#include <cuda_bf16.h>
#include <cstdint>
#include <math.h>

#define T_STEPS 2048
#define B_ROWS  64
#define TNO     501
#define NBASIS  30
#define ACC_N   512     // far-delay accumulator ring (power of 2 > TNO)
#define ACC_M   511
#define NTH     128     // 4 warps: key-chain / sub+uniform / decision+scatter / init

// ---------------------------------------------------------------------------
// Threefry-2x32, 20 rounds — bit-exact port of jax/_src/prng.py threefry2x32
// ---------------------------------------------------------------------------
__device__ __forceinline__ void tf2x32(uint32_t k0, uint32_t k1,
                                       uint32_t x0, uint32_t x1,
                                       uint32_t &o0, uint32_t &o1) {
    uint32_t k2 = k0 ^ k1 ^ 0x1BD11BDAu;
#define TFR(r) { x0 += x1; x1 = __funnelshift_l(x1, x1, (r)); x1 ^= x0; }
    x0 += k0; x1 += k1;
    TFR(13) TFR(15) TFR(26) TFR(6)
    x0 += k1; x1 += k2 + 1u;
    TFR(17) TFR(29) TFR(16) TFR(24)
    x0 += k2; x1 += k0 + 2u;
    TFR(13) TFR(15) TFR(26) TFR(6)
    x0 += k0; x1 += k1 + 3u;
    TFR(17) TFR(29) TFR(16) TFR(24)
    x0 += k1; x1 += k2 + 4u;
    TFR(13) TFR(15) TFR(26) TFR(6)
    x0 += k2; x1 += k0 + 5u;
#undef TFR
    o0 = x0; o1 = x1;
}

// XLA EmitTanh (Eigen rational, clamp [-9,9], |x|<4e-4 -> x), UNcontracted.
// This exact form gave rel_err 8e-8 (zero Bernoulli flips). DO NOT TOUCH.
__device__ __forceinline__ float tanh_xla(float x) {
    float ax = fabsf(x);
    float xc = fminf(fmaxf(x, -9.0f), 9.0f);
    float x2 = __fmul_rn(xc, xc);
    float num = -2.76076847742355e-16f;
    num = __fadd_rn(__fmul_rn(x2, num),  2.00018790482477e-13f);
    num = __fadd_rn(__fmul_rn(x2, num), -8.60467152213735e-11f);
    num = __fadd_rn(__fmul_rn(x2, num),  5.12229709037114e-08f);
    num = __fadd_rn(__fmul_rn(x2, num),  1.48572235717979e-05f);
    num = __fadd_rn(__fmul_rn(x2, num),  6.37261928875436e-04f);
    num = __fadd_rn(__fmul_rn(x2, num),  4.89352455891786e-03f);
    num = __fmul_rn(xc, num);
    float den = 1.19825839466702e-06f;
    den = __fadd_rn(__fmul_rn(x2, den),  1.18534705686654e-04f);
    den = __fadd_rn(__fmul_rn(x2, den),  2.26843463243900e-03f);
    den = __fadd_rn(__fmul_rn(x2, den),  4.89352518554385e-03f);
    float r = __fdiv_rn(num, den);
    return (ax < 0.0004f) ? x : r;
}
// P = 0.5*tanh(0.5*x)+0.5  (bit-identical to the passing kernel's sequence)
__device__ __forceinline__ float sigP(float x) {
    return __fadd_rn(__fmul_rn(0.5f, tanh_xla(__fmul_rn(0.5f, x))), 0.5f);
}

__device__ __forceinline__ void st_rel(int *p, int v) {
    uint32_t a = (uint32_t)__cvta_generic_to_shared(p);
    asm volatile("st.release.cta.shared.b32 [%0], %1;" :: "r"(a), "r"(v) : "memory");
}
__device__ __forceinline__ int ldv(volatile int *p) { return *p; }

// ---------------------------------------------------------------------------
// One block per row b.  4 warps:
//   warp0 lane0   : key chain ONLY: key <- tf(key,(0,0)); keys to smem ring.
//                   Serial dep chain ~180 cy/step — the system floor.
//   warp1 lanes0-3: sub+uniform: sub = tf(key,(0,1)); u = tf(sub,(0,b)).
//                   2 serial tf per lane per 4 steps (~90 cy/step).
//   warp2 (all 32): decision+scatter. Lane L computes candidate P(t|mask=L)
//                   (validated sequence) AND pre-compares sp_cand = u(t)<P;
//                   ballot -> W[t].  Resolution of s(t-5) = pure bit-ops on
//                   uniform regs (~16cy/step).  Scatter + acc hazards are
//                   enforced by program order — ZERO flags on the recurrence.
//   warp3         : init help only
// ---------------------------------------------------------------------------
__global__ __launch_bounds__(NTH)
void apnn_kernel(const float *__restrict__ V,  const float *__restrict__ D,
                 const float *__restrict__ w1, const float *__restrict__ b1,
                 const float *__restrict__ w2, const float *__restrict__ b2,
                 const float *__restrict__ Wref, float *__restrict__ out) {
    __shared__ float    nnrow[T_STEPS];          // MLP output, this row
    __shared__ uint32_t keyring[T_STEPS][2];     // key_t (pre-split)
    __shared__ float    uring[T_STEPS];          // per-step uniforms
    __shared__ float    acc[ACC_N];              // pending far refract
    __shared__ float    wdel[TNO];               // weight for delay j+1
    __shared__ int      chain_seq, u_seq;

    const int tid = threadIdx.x;
    const int wid = tid >> 5;
    const int b   = blockIdx.x;

    if (tid == 0) { chain_seq = 0; u_seq = 0; }
    __syncthreads();

    if (tid == 0) {
        // ---- key chain: ONLY the serial recurrence key <- tf(key,(0,0)).
        uint32_t k0 = 0u, k1 = 42u;              // jax.random.key(42) -> (0,42)
        for (int base = 0; base < T_STEPS; base += 4) {
            #pragma unroll
            for (int q = 0; q < 4; q++) {
                keyring[base + q][0] = k0;       // key_t stored BEFORE advance
                keyring[base + q][1] = k1;
                uint32_t nk0, nk1;
                tf2x32(k0, k1, 0u, 0u, nk0, nk1);
                k0 = nk0; k1 = nk1;
            }
            st_rel(&chain_seq, base + 4);
        }
    } else if (tid >= 32 && tid < 36) {
        // ---- sub+uniform: lane handles t = base+lane; two serial tf.
        const int lane = tid - 32;
        int cs = 0;
        for (int base = 0; base < T_STEPS; base += 4) {
            if (cs < base + 4) { do { cs = ldv(&chain_seq); } while (cs < base + 4); }
            int t = base + lane;
            uint32_t k0 = keyring[t][0];
            uint32_t k1 = keyring[t][1];
            uint32_t s0, s1, y0, y1;
            tf2x32(k0, k1, 0u, 1u, s0, s1);          // sub_t = tf(key,(0,1))
            tf2x32(s0, s1, 0u, (uint32_t)b, y0, y1); // bits = tf(sub,(0,b))
            uint32_t bits = y0 ^ y1;
            uring[t] = __uint_as_float((bits >> 9) | 0x3F800000u) - 1.0f;
            __syncwarp(0xFu);
            if (lane == 0) st_rel(&u_seq, base + 4);
        }
    } else if (tid >= 64) {
        // ---- init on warps 2+3 (64 threads), overlapped with chain/uniform
        const int itid = tid - 64;
        for (int i = itid; i < ACC_N; i += 64) acc[i] = 0.0f;
        // refractory delay weights: wdel[j] = sum_i f32(basis_f64[i,j])*Wref[i]
        for (int j = itid; j < TNO; j += 64) {
            double raw = 7.5 * log(((double)j + 1.0) + 1e-7);
            double cr = cos(raw), sr = sin(raw);
            float s = 0.0f;
            #pragma unroll 1
            for (int i = 0; i < NBASIS; i++) {
                double phi = 1.5707963267948966 * (double)i;
                float bas = 0.0f;
                if (!(raw < phi - 3.141592653589793 || raw > phi + 3.141592653589793)) {
                    double cv;
                    switch (i & 3) {
                        case 0:  cv =  cr; break;
                        case 1:  cv =  sr; break;
                        case 2:  cv = -cr; break;
                        default: cv = -sr; break;
                    }
                    bas = (float)(0.5 * cv + 0.5);
                }
                s = __fmaf_rn(bas, Wref[i], s);
            }
            wdel[j] = s;
        }
        // pointwise MLP (validated math)
        {
            float a0 = w1[0], a1 = w1[1], a2 = w1[2], a3 = w1[3], a4 = w1[4];
            float a5 = w1[5], a6 = w1[6], a7 = w1[7], a8 = w1[8], a9 = w1[9];
            float c0 = b1[0], c1 = b1[1], c2 = b1[2], c3 = b1[3], c4 = b1[4];
            float v0 = w2[0], v1 = w2[1], v2 = w2[2], v3 = w2[3], v4 = w2[4];
            float bb = b2[0];
            const float *Vr = V + (size_t)b * T_STEPS;
            const float *Dr = D + (size_t)b * T_STEPS;
            for (int t = itid; t < T_STEPS; t += 64) {
                float vv = Vr[t], dd = Dr[t];
                float h0 = tanh_xla(__fadd_rn(__fadd_rn(__fmul_rn(a0, vv), __fmul_rn(a1, dd)), c0));
                float h1 = tanh_xla(__fadd_rn(__fadd_rn(__fmul_rn(a2, vv), __fmul_rn(a3, dd)), c1));
                float h2 = tanh_xla(__fadd_rn(__fadd_rn(__fmul_rn(a4, vv), __fmul_rn(a5, dd)), c2));
                float h3 = tanh_xla(__fadd_rn(__fadd_rn(__fmul_rn(a6, vv), __fmul_rn(a7, dd)), c3));
                float h4 = tanh_xla(__fadd_rn(__fadd_rn(__fmul_rn(a8, vv), __fmul_rn(a9, dd)), c4));
                float s = __fmul_rn(v0, h0);
                s = __fadd_rn(s, __fmul_rn(v1, h1));
                s = __fadd_rn(s, __fmul_rn(v2, h2));
                s = __fadd_rn(s, __fmul_rn(v3, h3));
                s = __fadd_rn(s, __fmul_rn(v4, h4));
                nnrow[t] = __fadd_rn(s, bb);
            }
        }
        asm volatile("bar.sync 1, 64;" ::: "memory");   // warps 2+3

        if (wid == 2) {
            // ---- decision+scatter warp: ballot speculation, bit-op recurrence
            const int lane = tid & 31;
            const bool c0 = lane & 1, c1 = lane & 2, c2 = lane & 4,
                       c3 = lane & 8, c4 = lane & 16;
            const float wd0 = wdel[0],  wd1 = wdel[1],  wd2 = wdel[2];
            const float wd3 = wdel[3],  wd4 = wdel[4],  wd5 = wdel[5];
            const float wd6 = wdel[6],  wd7 = wdel[7],  wd8 = wdel[8];
            const float wd9 = wdel[9],  wd10 = wdel[10], wd11 = wdel[11];
            float wreg[16];                       // far delays d = 13+lane+32j
            #pragma unroll
            for (int j = 0; j < 16; j++) {
                int d = 13 + lane + 32 * j;
                wreg[j] = (d <= TNO) ? wdel[d - 1] : 0.0f;
            }
            float g6 = 0.f, g7 = 0.f, g8 = 0.f, g9 = 0.f,
                  g10 = 0.f, g11 = 0.f, g12 = 0.f;
            float    Pc[8];                       // candidate floats (ring)
            uint32_t Wb[8];                       // ballot words (ring)
            #pragma unroll
            for (int i = 0; i < 8; i++) { Pc[i] = 0.f; Wb[i] = 0u; }
            float sp_prev6 = 0.f;                 // s(t-6) for tail update
            unsigned m = 0;                       // realized 5-bit mask
            float *Sout = out + (size_t)b * T_STEPS;
            float *Pout = out + (size_t)B_ROWS * T_STEPS + (size_t)b * T_STEPS;
            int us = 0;
            for (int B = 0; B < T_STEPS; B += 8) {
                if (us < B + 8) { do { us = ldv(&u_seq); } while (us < B + 8); }
                // batch prefetch (latencies overlap).  acc[B..B+7] is complete:
                // contributing spikes <= B+7-13 resolved >= 8 slots ago in THIS
                // warp's program order.  In-batch scatters target >= B+8.
                float uu[8], nnv[8], fr[8];
                #pragma unroll
                for (int q = 0; q < 8; q++) uu[q] = uring[B + q];
                #pragma unroll
                for (int q = 0; q < 8; q++) nnv[q] = nnrow[B + q];
                #pragma unroll
                for (int q = 0; q < 8; q++) fr[q] = acc[(B + q) & ACC_M];
                if (lane == 0) {
                    #pragma unroll
                    for (int q = 0; q < 8; q++) acc[(B + q) & ACC_M] = 0.0f;
                }
                float myS = 0.f, myP = 0.f;       // per-lane batch outputs
                #pragma unroll
                for (int p = 0; p < 8; p++) {
                    const int t  = B + p;
                    const int t5 = t - 5;
                    // 1) resolve s(t5): pure bit-ops on uniform registers.
                    unsigned mo    = m;
                    unsigned spbit = (Wb[(p + 3) & 7] >> mo) & 1u;  // 0 if t5<0
                    m = ((mo << 1) | spbit) & 31u;
                    float spf = spbit ? 1.0f : 0.0f;
                    // 2) off-path P float for output (same value as validated)
                    float Pv = __shfl_sync(0xFFFFFFFFu, Pc[(p + 3) & 7], (int)mo);
                    if (lane == p) { myS = spf; myP = Pv; }
                    // 3) in-warp far scatter (uniform branch; spbit=0 if t5<0)
                    if (spbit) {
                        #pragma unroll
                        for (int j = 0; j < 16; j++) {
                            int d = 13 + lane + 32 * j;
                            if (d <= TNO) {
                                int s2 = (t5 + d) & ACC_M;   // conflict-free
                                acc[s2] = __fmaf_rn(wreg[j], spf, acc[s2]);
                            }
                        }
                    }
                    // 4) tail update with s(t-6) (resolved last slot)
                    g6  = __fmaf_rn(wd5,  sp_prev6, g7);
                    g7  = __fmaf_rn(wd6,  sp_prev6, g8);
                    g8  = __fmaf_rn(wd7,  sp_prev6, g9);
                    g9  = __fmaf_rn(wd8,  sp_prev6, g10);
                    g10 = __fmaf_rn(wd9,  sp_prev6, g11);
                    g11 = __fmaf_rn(wd10, sp_prev6, g12);
                    g12 = __fmul_rn(wd11, sp_prev6);
                    sp_prev6 = spf;               // = s(t-5) for next slot
                    // 5) candidate (validated rounding sequence)
                    float v = g6;
                    if (c4) v = __fadd_rn(wd4, v);
                    if (c3) v = __fadd_rn(wd3, v);
                    if (c2) v = __fadd_rn(wd2, v);
                    if (c1) v = __fadd_rn(wd1, v);
                    if (c0) v = __fadd_rn(wd0, v);
                    float x = __fadd_rn(nnv[p], __fadd_rn(fr[p], v));
                    float newP = sigP(x);
                    Pc[p] = newP;
                    // 6) pre-compare + ballot (future resolve becomes bit-ops)
                    bool spc = (uu[p] < newP);
                    Wb[p] = __ballot_sync(0xFFFFFFFFu, spc);
                }
                // 7) batch output: lanes 0..7 store (coalesced, off recurrence)
                {
                    int to = B + lane - 5;
                    if (lane < 8 && to >= 0) { Sout[to] = myS; Pout[to] = myP; }
                }
            }
            // epilogue: resolve t5 = T-5..T-1 from the last-written rings
            #pragma unroll
            for (int e = 0; e < 5; e++) {
                int t5 = T_STEPS - 5 + e;
                int idx = t5 & 7;
                unsigned mo    = m;
                unsigned spbit = (Wb[idx] >> mo) & 1u;
                m = ((mo << 1) | spbit) & 31u;
                float Pv = __shfl_sync(0xFFFFFFFFu, Pc[idx], (int)mo);
                if (lane == 0) {
                    Sout[t5] = spbit ? 1.0f : 0.0f;
                    Pout[t5] = Pv;
                }
            }
        }
        // warp3: done after init/bar
    }
}

extern "C" void kernel_launch(void* const* d_in, const int* in_sizes, int n_in,
                              void* d_out, int out_size) {
    const float *V    = (const float*)d_in[0];
    const float *D    = (const float*)d_in[1];
    const float *w1   = (const float*)d_in[2];
    const float *b1   = (const float*)d_in[3];
    const float *w2   = (const float*)d_in[4];
    const float *b2   = (const float*)d_in[5];
    const float *Wref = (const float*)d_in[6];
    float *out = (float*)d_out;
    apnn_kernel<<<B_ROWS, NTH>>>(V, D, w1, b1, w2, b2, Wref, out);
}